// round 1
// baseline (speedup 1.0000x reference)
#include <cuda_runtime.h>
#include <cuda_bf16.h>

// Problem constants: B=2, S=2048, D=1024, H=16, HD=64
#define BB 2
#define SS 2048
#define DD 1024
#define NH 16
#define HD 64

// Scratch (allocation-free rule: __device__ globals)
__device__ float g_qkv[(size_t)BB * SS * 3 * DD];  // [B, S, 3D]
__device__ float g_y[(size_t)BB * SS * DD];        // [B, S, D]

// ---------------------------------------------------------------------------
// Generic fp32 GEMM: C[M,N] = A[M,K] @ B[K,N], row-major.
// 64x64 block tile, BK=16, 256 threads, 4x4 micro-tile per thread.
// Assumes M%64==0, N%64==0, K%16==0 (true for all three calls).
// ---------------------------------------------------------------------------
__global__ __launch_bounds__(256) void gemm_kernel(
    const float* __restrict__ A, const float* __restrict__ Bm,
    float* __restrict__ C, int M, int N, int K)
{
    __shared__ float As[16][64];
    __shared__ float Bs[16][64];

    const int tid = threadIdx.x;
    const int tx = tid & 15;       // 0..15 -> output cols tx*4..+3
    const int ty = tid >> 4;       // 0..15 -> output rows ty*4..+3
    const int row0 = blockIdx.y * 64;
    const int col0 = blockIdx.x * 64;

    const int a_r = tid >> 2;        // 0..63
    const int a_c = (tid & 3) * 4;   // 0,4,8,12
    const int b_r = tid >> 4;        // 0..15
    const int b_c = (tid & 15) * 4;  // 0..60

    float acc[4][4] = {};

    for (int k0 = 0; k0 < K; k0 += 16) {
        float4 av = *reinterpret_cast<const float4*>(
            &A[(size_t)(row0 + a_r) * K + k0 + a_c]);
        float4 bv = *reinterpret_cast<const float4*>(
            &Bm[(size_t)(k0 + b_r) * N + col0 + b_c]);

        As[a_c + 0][a_r] = av.x;
        As[a_c + 1][a_r] = av.y;
        As[a_c + 2][a_r] = av.z;
        As[a_c + 3][a_r] = av.w;
        *reinterpret_cast<float4*>(&Bs[b_r][b_c]) = bv;
        __syncthreads();

        #pragma unroll
        for (int kk = 0; kk < 16; kk++) {
            float4 a4 = *reinterpret_cast<const float4*>(&As[kk][ty * 4]);
            float4 b4 = *reinterpret_cast<const float4*>(&Bs[kk][tx * 4]);
            float ar[4] = {a4.x, a4.y, a4.z, a4.w};
            float br[4] = {b4.x, b4.y, b4.z, b4.w};
            #pragma unroll
            for (int i = 0; i < 4; i++)
                #pragma unroll
                for (int j = 0; j < 4; j++)
                    acc[i][j] += ar[i] * br[j];
        }
        __syncthreads();
    }

    #pragma unroll
    for (int i = 0; i < 4; i++) {
        float4 o = make_float4(acc[i][0], acc[i][1], acc[i][2], acc[i][3]);
        *reinterpret_cast<float4*>(
            &C[(size_t)(row0 + ty * 4 + i) * N + col0 + tx * 4]) = o;
    }
}

// ---------------------------------------------------------------------------
// Causal flash attention, fp32. One CTA = 64 query rows of one (b,h).
// 64 threads, one query row per thread; q[64] and acc[64] in registers.
// K/V tiles (64x64) staged in smem; inner loops use broadcast LDS
// (all lanes read ks[j][*] -> conflict-free).
// ---------------------------------------------------------------------------
__global__ __launch_bounds__(64) void attn_kernel(
    const float* __restrict__ qkv, float* __restrict__ y)
{
    __shared__ float ks[64][64];
    __shared__ float vs[64][64];

    const int t = threadIdx.x;          // 0..63
    const int bh = blockIdx.y;          // 0..31
    const int b = bh >> 4;
    const int h = bh & 15;
    const int qb = blockIdx.x;          // query block
    const int i = qb * 64 + t;          // this thread's query row

    const float scale = 0.125f;         // 1/sqrt(64)

    // Load q row into registers, pre-scaled
    float q[64];
    const float* qp = qkv + (size_t)(b * SS + i) * (3 * DD) + h * HD;
    #pragma unroll
    for (int d4 = 0; d4 < 16; d4++) {
        float4 v4 = *reinterpret_cast<const float4*>(qp + d4 * 4);
        q[d4 * 4 + 0] = v4.x * scale;
        q[d4 * 4 + 1] = v4.y * scale;
        q[d4 * 4 + 2] = v4.z * scale;
        q[d4 * 4 + 3] = v4.w * scale;
    }

    float m = -1e30f;
    float l = 0.0f;
    float acc[64] = {};

    const int lr = t >> 4;              // 0..3 (row within 4-row group)
    const int lc = (t & 15) * 4;        // 0..60 (float4 column)

    for (int jb = 0; jb <= qb; jb++) {
        const int j0 = jb * 64;
        const float* kbase = qkv + ((size_t)(b * SS) + j0) * (3 * DD) + DD + h * HD;
        const float* vbase = kbase + DD;

        // Cooperative coalesced tile load: 16 threads per row, 4 rows/pass
        #pragma unroll
        for (int r = 0; r < 64; r += 4) {
            int row = r + lr;
            *reinterpret_cast<float4*>(&ks[row][lc]) =
                *reinterpret_cast<const float4*>(kbase + (size_t)row * (3 * DD) + lc);
            *reinterpret_cast<float4*>(&vs[row][lc]) =
                *reinterpret_cast<const float4*>(vbase + (size_t)row * (3 * DD) + lc);
        }
        __syncthreads();

        int jmax = i - j0 + 1;
        if (jmax > 64) jmax = 64;

        for (int j = 0; j < jmax; j++) {
            float s = 0.0f;
            #pragma unroll
            for (int d4 = 0; d4 < 16; d4++) {
                float4 kv = *reinterpret_cast<const float4*>(&ks[j][d4 * 4]);
                s += q[d4 * 4 + 0] * kv.x + q[d4 * 4 + 1] * kv.y
                   + q[d4 * 4 + 2] * kv.z + q[d4 * 4 + 3] * kv.w;
            }
            if (s > m) {
                // New running max: rescale accumulator (rare; ~ln(S) per row)
                float c = __expf(m - s);
                m = s;
                l = l * c + 1.0f;
                #pragma unroll
                for (int d4 = 0; d4 < 16; d4++) {
                    float4 vv = *reinterpret_cast<const float4*>(&vs[j][d4 * 4]);
                    acc[d4 * 4 + 0] = acc[d4 * 4 + 0] * c + vv.x;
                    acc[d4 * 4 + 1] = acc[d4 * 4 + 1] * c + vv.y;
                    acc[d4 * 4 + 2] = acc[d4 * 4 + 2] * c + vv.z;
                    acc[d4 * 4 + 3] = acc[d4 * 4 + 3] * c + vv.w;
                }
            } else {
                float p = __expf(s - m);
                l += p;
                #pragma unroll
                for (int d4 = 0; d4 < 16; d4++) {
                    float4 vv = *reinterpret_cast<const float4*>(&vs[j][d4 * 4]);
                    acc[d4 * 4 + 0] += p * vv.x;
                    acc[d4 * 4 + 1] += p * vv.y;
                    acc[d4 * 4 + 2] += p * vv.z;
                    acc[d4 * 4 + 3] += p * vv.w;
                }
            }
        }
        __syncthreads();
    }

    const float inv = 1.0f / l;
    float* yp = y + (size_t)(b * SS + i) * DD + h * HD;
    #pragma unroll
    for (int d4 = 0; d4 < 16; d4++) {
        float4 o = make_float4(acc[d4 * 4 + 0] * inv, acc[d4 * 4 + 1] * inv,
                               acc[d4 * 4 + 2] * inv, acc[d4 * 4 + 3] * inv);
        *reinterpret_cast<float4*>(yp + d4 * 4) = o;
    }
}

// ---------------------------------------------------------------------------
// Launch: qkv = x @ w_qkv ; attention ; out = y @ w_proj
// ---------------------------------------------------------------------------
extern "C" void kernel_launch(void* const* d_in, const int* in_sizes, int n_in,
                              void* d_out, int out_size)
{
    const float* x      = (const float*)d_in[0];   // [2,2048,1024]
    const float* w_qkv  = (const float*)d_in[1];   // [1024,3072]
    const float* w_proj = (const float*)d_in[2];   // [1024,1024]
    float* out = (float*)d_out;                    // [2,2048,1024]

    float* qkv_ptr = nullptr;
    float* y_ptr = nullptr;
    cudaGetSymbolAddress((void**)&qkv_ptr, g_qkv);
    cudaGetSymbolAddress((void**)&y_ptr, g_y);

    const int M = BB * SS;  // 4096

    // qkv = x @ w_qkv : [4096,1024]x[1024,3072]
    gemm_kernel<<<dim3((3 * DD) / 64, M / 64), 256>>>(x, w_qkv, qkv_ptr, M, 3 * DD, DD);

    // attention: grid (S/64 query blocks, B*H)
    attn_kernel<<<dim3(SS / 64, BB * NH), 64>>>(qkv_ptr, y_ptr);

    // out = y @ w_proj : [4096,1024]x[1024,1024]
    gemm_kernel<<<dim3(DD / 64, M / 64), 256>>>(y_ptr, w_proj, out, M, DD, DD);
}

// round 3
// speedup vs baseline: 1.4397x; 1.4397x over previous
#include <cuda_runtime.h>
#include <cuda_bf16.h>
#include <cstdint>

// Problem constants: B=2, S=2048, D=1024, H=16, HD=64
#define BB 2
#define SS 2048
#define DD 1024
#define NH 16
#define HD 64

// ---------------------------------------------------------------------------
// mma.sync / ldmatrix helpers (plain PTX, no sm_103a-gated features)
// ---------------------------------------------------------------------------
__device__ __forceinline__ uint32_t smem_u32(const void* p) {
    uint32_t a;
    asm("{ .reg .u64 t; cvta.to.shared.u64 t, %1; cvt.u32.u64 %0, t; }"
        : "=r"(a) : "l"(p));
    return a;
}
__device__ __forceinline__ void ldsm_x4(uint32_t* r, uint32_t addr) {
    asm volatile("ldmatrix.sync.aligned.m8n8.x4.shared.b16 {%0,%1,%2,%3}, [%4];"
        : "=r"(r[0]), "=r"(r[1]), "=r"(r[2]), "=r"(r[3]) : "r"(addr));
}
__device__ __forceinline__ void mma16816(float* c, const uint32_t* a,
                                         uint32_t b0, uint32_t b1) {
    asm volatile(
        "mma.sync.aligned.m16n8k16.row.col.f32.bf16.bf16.f32 "
        "{%0,%1,%2,%3}, {%4,%5,%6,%7}, {%8,%9}, {%0,%1,%2,%3};"
        : "+f"(c[0]), "+f"(c[1]), "+f"(c[2]), "+f"(c[3])
        : "r"(a[0]), "r"(a[1]), "r"(a[2]), "r"(a[3]), "r"(b0), "r"(b1));
}

// ---------------------------------------------------------------------------
// Scratch (__device__ globals; allocation-free rule)
// ---------------------------------------------------------------------------
__device__ float g_qkv[(size_t)BB * SS * 3 * DD];       // [4096, 3072]
__device__ float g_y[(size_t)BB * SS * DD];             // [4096, 1024]
__device__ __nv_bfloat16 g_xhi[(size_t)BB * SS * DD];
__device__ __nv_bfloat16 g_xlo[(size_t)BB * SS * DD];
__device__ __nv_bfloat16 g_yhi[(size_t)BB * SS * DD];
__device__ __nv_bfloat16 g_ylo[(size_t)BB * SS * DD];
__device__ __nv_bfloat16 g_wqkvT_hi[(size_t)3 * DD * DD];  // [3072, 1024] K-major
__device__ __nv_bfloat16 g_wqkvT_lo[(size_t)3 * DD * DD];
__device__ __nv_bfloat16 g_wprojT_hi[(size_t)DD * DD];     // [1024, 1024] K-major
__device__ __nv_bfloat16 g_wprojT_lo[(size_t)DD * DD];

// ---------------------------------------------------------------------------
// Elementwise fp32 -> bf16 hi/lo split
// ---------------------------------------------------------------------------
__global__ __launch_bounds__(256) void split_kernel(
    const float* __restrict__ in, __nv_bfloat16* __restrict__ hi,
    __nv_bfloat16* __restrict__ lo, int n)
{
    int i = blockIdx.x * 256 + threadIdx.x;
    if (i < n) {
        float v = in[i];
        __nv_bfloat16 h = __float2bfloat16(v);
        hi[i] = h;
        lo[i] = __float2bfloat16(v - __bfloat162float(h));
    }
}

// ---------------------------------------------------------------------------
// Transpose + split: in [K,N] fp32 -> hiT/loT [N,K] bf16 (K-major)
// ---------------------------------------------------------------------------
__global__ __launch_bounds__(256) void transpose_split_kernel(
    const float* __restrict__ in, __nv_bfloat16* __restrict__ hiT,
    __nv_bfloat16* __restrict__ loT, int K, int N)
{
    __shared__ float t[32][33];
    const int tx = threadIdx.x & 31;
    const int ty = threadIdx.x >> 5;   // 0..7
    const int n0 = blockIdx.x * 32;
    const int k0 = blockIdx.y * 32;
    #pragma unroll
    for (int i = 0; i < 4; i++) {
        int k = k0 + ty + i * 8;
        t[ty + i * 8][tx] = in[(size_t)k * N + n0 + tx];
    }
    __syncthreads();
    #pragma unroll
    for (int i = 0; i < 4; i++) {
        int n = n0 + ty + i * 8;
        int k = k0 + tx;
        float v = t[tx][ty + i * 8];
        __nv_bfloat16 h = __float2bfloat16(v);
        hiT[(size_t)n * K + k] = h;
        loT[(size_t)n * K + k] = __float2bfloat16(v - __bfloat162float(h));
    }
}

// ---------------------------------------------------------------------------
// bf16-split GEMM via mma.sync: C[M,N] = (Ahi+Alo)[M,K] @ (Bhi+Blo)[N,K]^T
// D = Ahi*Bhi + Ahi*Blo + Alo*Bhi, fp32 accumulate (rel err ~2^-16).
// CTA tile 128x128, BK=32, 256 threads = 8 warps (2 x 4), warp tile 64x32.
// Smem rows padded to 80B (stride 5 x 16B units, mod-8 covers all bank
// groups -> conflict-free ldmatrix).
// ---------------------------------------------------------------------------
#define ROWB 80
#define SA_HI 0
#define SA_LO 10240
#define SB_HI 20480
#define SB_LO 30720

__global__ __launch_bounds__(256) void mma_gemm_kernel(
    const __nv_bfloat16* __restrict__ Ahi, const __nv_bfloat16* __restrict__ Alo,
    const __nv_bfloat16* __restrict__ Bhi, const __nv_bfloat16* __restrict__ Blo,
    float* __restrict__ C, int Ntot, int K)
{
    __shared__ __align__(16) char sm[4 * 128 * ROWB];   // 40960 B

    const int tid = threadIdx.x;
    const int wid = tid >> 5;
    const int lane = tid & 31;
    const int warp_m = wid >> 2;         // 0..1 -> rows warp_m*64
    const int warp_n = wid & 3;          // 0..3 -> cols warp_n*32
    const int row0 = blockIdx.y * 128;
    const int col0 = blockIdx.x * 128;

    const uint32_t smA_hi = smem_u32(sm) + SA_HI;
    const uint32_t smA_lo = smem_u32(sm) + SA_LO;
    const uint32_t smB_hi = smem_u32(sm) + SB_HI;
    const uint32_t smB_lo = smem_u32(sm) + SB_LO;

    // ldmatrix lane addressing offsets
    // A (m16 x k16 block): row = base + lane%16, k-half by lane>>4
    const uint32_t a_lane_off = (uint32_t)(lane & 15) * ROWB + ((lane >> 4) & 1) * 16;
    // B (n16 x k16 pair): n = nb + lane%8 + ((lane>>4)&1)*8, k-half by (lane>>3)&1
    const uint32_t b_lane_off = ((uint32_t)((lane & 7) + ((lane >> 4) & 1) * 8)) * ROWB
                              + ((lane >> 3) & 1) * 16;

    float acc[4][4][4] = {};

    const int nchunks = K >> 5;          // BK = 32
    for (int kc = 0; kc < nchunks; kc++) {
        const int k0 = kc << 5;
        // Load 4 tiles (A hi/lo 128x32, B hi/lo 128x32), 2 uint4 per thread per tile
        #pragma unroll
        for (int i = 0; i < 2; i++) {
            int u = tid + (i << 8);            // 0..511
            int r = u >> 2, c = u & 3;
            uint32_t dst = (uint32_t)r * ROWB + (uint32_t)c * 16;
            size_t asrc = (size_t)(row0 + r) * K + k0 + c * 8;
            size_t bsrc = (size_t)(col0 + r) * K + k0 + c * 8;
            *reinterpret_cast<uint4*>(sm + SA_HI + dst) =
                *reinterpret_cast<const uint4*>(Ahi + asrc);
            *reinterpret_cast<uint4*>(sm + SA_LO + dst) =
                *reinterpret_cast<const uint4*>(Alo + asrc);
            *reinterpret_cast<uint4*>(sm + SB_HI + dst) =
                *reinterpret_cast<const uint4*>(Bhi + bsrc);
            *reinterpret_cast<uint4*>(sm + SB_LO + dst) =
                *reinterpret_cast<const uint4*>(Blo + bsrc);
        }
        __syncthreads();

        #pragma unroll
        for (int ks = 0; ks < 2; ks++) {
            const uint32_t koff = (uint32_t)ks * 32;
            uint32_t ah[4][4], al[4][4], bh[2][4], bl[2][4];
            #pragma unroll
            for (int mm = 0; mm < 4; mm++) {
                uint32_t ab = (uint32_t)(warp_m * 64 + mm * 16) * ROWB + koff + a_lane_off;
                ldsm_x4(ah[mm], smA_hi + ab);
                ldsm_x4(al[mm], smA_lo + ab);
            }
            #pragma unroll
            for (int pr = 0; pr < 2; pr++) {
                uint32_t bb = (uint32_t)(warp_n * 32 + pr * 16) * ROWB + koff + b_lane_off;
                ldsm_x4(bh[pr], smB_hi + bb);
                ldsm_x4(bl[pr], smB_lo + bb);
            }
            #pragma unroll
            for (int mm = 0; mm < 4; mm++) {
                #pragma unroll
                for (int nn = 0; nn < 4; nn++) {
                    const int pr = nn >> 1, sb2 = (nn & 1) * 2;
                    mma16816(acc[mm][nn], ah[mm], bh[pr][sb2], bh[pr][sb2 + 1]);
                    mma16816(acc[mm][nn], ah[mm], bl[pr][sb2], bl[pr][sb2 + 1]);
                    mma16816(acc[mm][nn], al[mm], bh[pr][sb2], bh[pr][sb2 + 1]);
                }
            }
        }
        __syncthreads();
    }

    // Epilogue: c0,c1 -> (row g, col tq*2), c2,c3 -> (row g+8)
    const int g = lane >> 2, tq = lane & 3;
    #pragma unroll
    for (int mm = 0; mm < 4; mm++) {
        #pragma unroll
        for (int nn = 0; nn < 4; nn++) {
            int row = row0 + warp_m * 64 + mm * 16 + g;
            int col = col0 + warp_n * 32 + nn * 8 + tq * 2;
            *reinterpret_cast<float2*>(&C[(size_t)row * Ntot + col]) =
                make_float2(acc[mm][nn][0], acc[mm][nn][1]);
            *reinterpret_cast<float2*>(&C[(size_t)(row + 8) * Ntot + col]) =
                make_float2(acc[mm][nn][2], acc[mm][nn][3]);
        }
    }
}

// ---------------------------------------------------------------------------
// Causal flash attention, fp32 (at fp32 FMA roofline; tensor port next round)
// ---------------------------------------------------------------------------
__global__ __launch_bounds__(64) void attn_kernel(
    const float* __restrict__ qkv, float* __restrict__ y)
{
    __shared__ float ks[64][64];
    __shared__ float vs[64][64];

    const int t = threadIdx.x;
    const int bh = blockIdx.y;
    const int b = bh >> 4;
    const int h = bh & 15;
    const int qb = blockIdx.x;
    const int i = qb * 64 + t;

    const float scale = 0.125f;

    float q[64];
    const float* qp = qkv + (size_t)(b * SS + i) * (3 * DD) + h * HD;
    #pragma unroll
    for (int d4 = 0; d4 < 16; d4++) {
        float4 v4 = *reinterpret_cast<const float4*>(qp + d4 * 4);
        q[d4 * 4 + 0] = v4.x * scale;
        q[d4 * 4 + 1] = v4.y * scale;
        q[d4 * 4 + 2] = v4.z * scale;
        q[d4 * 4 + 3] = v4.w * scale;
    }

    float m = -1e30f;
    float l = 0.0f;
    float acc[64] = {};

    const int lr = t >> 4;
    const int lc = (t & 15) * 4;

    for (int jb = 0; jb <= qb; jb++) {
        const int j0 = jb * 64;
        const float* kbase = qkv + ((size_t)(b * SS) + j0) * (3 * DD) + DD + h * HD;
        const float* vbase = kbase + DD;

        #pragma unroll
        for (int r = 0; r < 64; r += 4) {
            int row = r + lr;
            *reinterpret_cast<float4*>(&ks[row][lc]) =
                *reinterpret_cast<const float4*>(kbase + (size_t)row * (3 * DD) + lc);
            *reinterpret_cast<float4*>(&vs[row][lc]) =
                *reinterpret_cast<const float4*>(vbase + (size_t)row * (3 * DD) + lc);
        }
        __syncthreads();

        int jmax = i - j0 + 1;
        if (jmax > 64) jmax = 64;

        for (int j = 0; j < jmax; j++) {
            float s = 0.0f;
            #pragma unroll
            for (int d4 = 0; d4 < 16; d4++) {
                float4 kv = *reinterpret_cast<const float4*>(&ks[j][d4 * 4]);
                s += q[d4 * 4 + 0] * kv.x + q[d4 * 4 + 1] * kv.y
                   + q[d4 * 4 + 2] * kv.z + q[d4 * 4 + 3] * kv.w;
            }
            if (s > m) {
                float c = __expf(m - s);
                m = s;
                l = l * c + 1.0f;
                #pragma unroll
                for (int d4 = 0; d4 < 16; d4++) {
                    float4 vv = *reinterpret_cast<const float4*>(&vs[j][d4 * 4]);
                    acc[d4 * 4 + 0] = acc[d4 * 4 + 0] * c + vv.x;
                    acc[d4 * 4 + 1] = acc[d4 * 4 + 1] * c + vv.y;
                    acc[d4 * 4 + 2] = acc[d4 * 4 + 2] * c + vv.z;
                    acc[d4 * 4 + 3] = acc[d4 * 4 + 3] * c + vv.w;
                }
            } else {
                float p = __expf(s - m);
                l += p;
                #pragma unroll
                for (int d4 = 0; d4 < 16; d4++) {
                    float4 vv = *reinterpret_cast<const float4*>(&vs[j][d4 * 4]);
                    acc[d4 * 4 + 0] += p * vv.x;
                    acc[d4 * 4 + 1] += p * vv.y;
                    acc[d4 * 4 + 2] += p * vv.z;
                    acc[d4 * 4 + 3] += p * vv.w;
                }
            }
        }
        __syncthreads();
    }

    const float inv = 1.0f / l;
    float* yp = y + (size_t)(b * SS + i) * DD + h * HD;
    #pragma unroll
    for (int d4 = 0; d4 < 16; d4++) {
        float4 o = make_float4(acc[d4 * 4 + 0] * inv, acc[d4 * 4 + 1] * inv,
                               acc[d4 * 4 + 2] * inv, acc[d4 * 4 + 3] * inv);
        *reinterpret_cast<float4*>(yp + d4 * 4) = o;
    }
}

// ---------------------------------------------------------------------------
// Launch
// ---------------------------------------------------------------------------
extern "C" void kernel_launch(void* const* d_in, const int* in_sizes, int n_in,
                              void* d_out, int out_size)
{
    const float* x      = (const float*)d_in[0];   // [2,2048,1024]
    const float* w_qkv  = (const float*)d_in[1];   // [1024,3072]
    const float* w_proj = (const float*)d_in[2];   // [1024,1024]
    float* out = (float*)d_out;                    // [2,2048,1024]

    float *qkv_ptr, *y_ptr;
    __nv_bfloat16 *xhi, *xlo, *yhi, *ylo, *wqT_hi, *wqT_lo, *wpT_hi, *wpT_lo;
    cudaGetSymbolAddress((void**)&qkv_ptr, g_qkv);
    cudaGetSymbolAddress((void**)&y_ptr, g_y);
    cudaGetSymbolAddress((void**)&xhi, g_xhi);
    cudaGetSymbolAddress((void**)&xlo, g_xlo);
    cudaGetSymbolAddress((void**)&yhi, g_yhi);
    cudaGetSymbolAddress((void**)&ylo, g_ylo);
    cudaGetSymbolAddress((void**)&wqT_hi, g_wqkvT_hi);
    cudaGetSymbolAddress((void**)&wqT_lo, g_wqkvT_lo);
    cudaGetSymbolAddress((void**)&wpT_hi, g_wprojT_hi);
    cudaGetSymbolAddress((void**)&wpT_lo, g_wprojT_lo);

    const int M = BB * SS;       // 4096
    const int nElemX = M * DD;   // 4 Mi

    // Conversions
    split_kernel<<<nElemX / 256, 256>>>(x, xhi, xlo, nElemX);
    transpose_split_kernel<<<dim3(3 * DD / 32, DD / 32), 256>>>(w_qkv, wqT_hi, wqT_lo, DD, 3 * DD);
    transpose_split_kernel<<<dim3(DD / 32, DD / 32), 256>>>(w_proj, wpT_hi, wpT_lo, DD, DD);

    // qkv = x @ w_qkv  (tensor cores via mma.sync, bf16-split)
    mma_gemm_kernel<<<dim3(3 * DD / 128, M / 128), 256>>>(
        xhi, xlo, wqT_hi, wqT_lo, qkv_ptr, 3 * DD, DD);

    // attention
    attn_kernel<<<dim3(SS / 64, BB * NH), 64>>>(qkv_ptr, y_ptr);

    // y split, then out = y @ w_proj
    split_kernel<<<nElemX / 256, 256>>>(y_ptr, yhi, ylo, nElemX);
    mma_gemm_kernel<<<dim3(DD / 128, M / 128), 256>>>(
        yhi, ylo, wpT_hi, wpT_lo, out, DD, DD);
}

// round 4
// speedup vs baseline: 2.0994x; 1.4582x over previous
#include <cuda_runtime.h>
#include <cuda_bf16.h>
#include <cstdint>

// Problem constants: B=2, S=2048, D=1024, H=16, HD=64
#define BB 2
#define SS 2048
#define DD 1024
#define NH 16
#define HD 64

// ---------------------------------------------------------------------------
// mma.sync / ldmatrix helpers (plain PTX, no sm_103a-gated features)
// ---------------------------------------------------------------------------
__device__ __forceinline__ uint32_t smem_u32(const void* p) {
    uint32_t a;
    asm("{ .reg .u64 t; cvta.to.shared.u64 t, %1; cvt.u32.u64 %0, t; }"
        : "=r"(a) : "l"(p));
    return a;
}
__device__ __forceinline__ void ldsm_x4(uint32_t* r, uint32_t addr) {
    asm volatile("ldmatrix.sync.aligned.m8n8.x4.shared.b16 {%0,%1,%2,%3}, [%4];"
        : "=r"(r[0]), "=r"(r[1]), "=r"(r[2]), "=r"(r[3]) : "r"(addr));
}
__device__ __forceinline__ void ldsm_x4_trans(uint32_t* r, uint32_t addr) {
    asm volatile("ldmatrix.sync.aligned.m8n8.x4.trans.shared.b16 {%0,%1,%2,%3}, [%4];"
        : "=r"(r[0]), "=r"(r[1]), "=r"(r[2]), "=r"(r[3]) : "r"(addr));
}
__device__ __forceinline__ void mma16816(float* c, const uint32_t* a,
                                         uint32_t b0, uint32_t b1) {
    asm volatile(
        "mma.sync.aligned.m16n8k16.row.col.f32.bf16.bf16.f32 "
        "{%0,%1,%2,%3}, {%4,%5,%6,%7}, {%8,%9}, {%0,%1,%2,%3};"
        : "+f"(c[0]), "+f"(c[1]), "+f"(c[2]), "+f"(c[3])
        : "r"(a[0]), "r"(a[1]), "r"(a[2]), "r"(a[3]), "r"(b0), "r"(b1));
}
// pack: low half = lo_elem, high half = hi_elem
__device__ __forceinline__ uint32_t pack_bf16x2(float lo_elem, float hi_elem) {
    uint32_t r;
    asm("cvt.rn.bf16x2.f32 %0, %1, %2;" : "=r"(r) : "f"(hi_elem), "f"(lo_elem));
    return r;
}
__device__ __forceinline__ float bf16_round(float v) {
    return __bfloat162float(__float2bfloat16(v));
}

// ---------------------------------------------------------------------------
// Scratch (__device__ globals; allocation-free rule)
// ---------------------------------------------------------------------------
__device__ __nv_bfloat16 g_xhi[(size_t)BB * SS * DD];
__device__ __nv_bfloat16 g_xlo[(size_t)BB * SS * DD];
__device__ __nv_bfloat16 g_qkvh[(size_t)BB * SS * 3 * DD];  // [4096, 3072]
__device__ __nv_bfloat16 g_qkvl[(size_t)BB * SS * 3 * DD];
__device__ __nv_bfloat16 g_yh[(size_t)BB * SS * DD];        // [4096, 1024]
__device__ __nv_bfloat16 g_yl[(size_t)BB * SS * DD];
__device__ __nv_bfloat16 g_wqkvT_hi[(size_t)3 * DD * DD];   // [3072, 1024] K-major
__device__ __nv_bfloat16 g_wqkvT_lo[(size_t)3 * DD * DD];
__device__ __nv_bfloat16 g_wprojT_hi[(size_t)DD * DD];      // [1024, 1024] K-major
__device__ __nv_bfloat16 g_wprojT_lo[(size_t)DD * DD];

// ---------------------------------------------------------------------------
// Elementwise fp32 -> bf16 hi/lo split (input x only)
// ---------------------------------------------------------------------------
__global__ __launch_bounds__(256) void split_kernel(
    const float* __restrict__ in, __nv_bfloat16* __restrict__ hi,
    __nv_bfloat16* __restrict__ lo, int n)
{
    int i = blockIdx.x * 256 + threadIdx.x;
    if (i < n) {
        float v = in[i];
        __nv_bfloat16 h = __float2bfloat16(v);
        hi[i] = h;
        lo[i] = __float2bfloat16(v - __bfloat162float(h));
    }
}

// ---------------------------------------------------------------------------
// Transpose + split: in [K,N] fp32 -> hiT/loT [N,K] bf16 (K-major)
// ---------------------------------------------------------------------------
__global__ __launch_bounds__(256) void transpose_split_kernel(
    const float* __restrict__ in, __nv_bfloat16* __restrict__ hiT,
    __nv_bfloat16* __restrict__ loT, int K, int N)
{
    __shared__ float t[32][33];
    const int tx = threadIdx.x & 31;
    const int ty = threadIdx.x >> 5;
    const int n0 = blockIdx.x * 32;
    const int k0 = blockIdx.y * 32;
    #pragma unroll
    for (int i = 0; i < 4; i++) {
        int k = k0 + ty + i * 8;
        t[ty + i * 8][tx] = in[(size_t)k * N + n0 + tx];
    }
    __syncthreads();
    #pragma unroll
    for (int i = 0; i < 4; i++) {
        int n = n0 + ty + i * 8;
        int k = k0 + tx;
        float v = t[tx][ty + i * 8];
        __nv_bfloat16 h = __float2bfloat16(v);
        hiT[(size_t)n * K + k] = h;
        loT[(size_t)n * K + k] = __float2bfloat16(v - __bfloat162float(h));
    }
}

// ---------------------------------------------------------------------------
// bf16-split GEMM via mma.sync: C = (Ahi+Alo)[M,K] @ (Bhi+Blo)[N,K]^T
// Output either fp32 (Cf) or bf16 hi/lo (Chi/Clo) when Chi != nullptr.
// CTA 128x128, BK=32, 256 threads (8 warps, 2x4), warp tile 64x32.
// ---------------------------------------------------------------------------
#define ROWB 80
#define SA_HI 0
#define SA_LO 10240
#define SB_HI 20480
#define SB_LO 30720

__global__ __launch_bounds__(256) void mma_gemm_kernel(
    const __nv_bfloat16* __restrict__ Ahi, const __nv_bfloat16* __restrict__ Alo,
    const __nv_bfloat16* __restrict__ Bhi, const __nv_bfloat16* __restrict__ Blo,
    float* __restrict__ Cf, __nv_bfloat16* __restrict__ Chi,
    __nv_bfloat16* __restrict__ Clo, int Ntot, int K)
{
    __shared__ __align__(16) char sm[4 * 128 * ROWB];

    const int tid = threadIdx.x;
    const int wid = tid >> 5;
    const int lane = tid & 31;
    const int warp_m = wid >> 2;
    const int warp_n = wid & 3;
    const int row0 = blockIdx.y * 128;
    const int col0 = blockIdx.x * 128;

    const uint32_t smA_hi = smem_u32(sm) + SA_HI;
    const uint32_t smA_lo = smem_u32(sm) + SA_LO;
    const uint32_t smB_hi = smem_u32(sm) + SB_HI;
    const uint32_t smB_lo = smem_u32(sm) + SB_LO;

    const uint32_t a_lane_off = (uint32_t)(lane & 15) * ROWB + ((lane >> 4) & 1) * 16;
    const uint32_t b_lane_off = ((uint32_t)((lane & 7) + ((lane >> 4) & 1) * 8)) * ROWB
                              + ((lane >> 3) & 1) * 16;

    float acc[4][4][4] = {};

    const int nchunks = K >> 5;
    for (int kc = 0; kc < nchunks; kc++) {
        const int k0 = kc << 5;
        #pragma unroll
        for (int i = 0; i < 2; i++) {
            int u = tid + (i << 8);
            int r = u >> 2, c = u & 3;
            uint32_t dst = (uint32_t)r * ROWB + (uint32_t)c * 16;
            size_t asrc = (size_t)(row0 + r) * K + k0 + c * 8;
            size_t bsrc = (size_t)(col0 + r) * K + k0 + c * 8;
            *reinterpret_cast<uint4*>(sm + SA_HI + dst) =
                *reinterpret_cast<const uint4*>(Ahi + asrc);
            *reinterpret_cast<uint4*>(sm + SA_LO + dst) =
                *reinterpret_cast<const uint4*>(Alo + asrc);
            *reinterpret_cast<uint4*>(sm + SB_HI + dst) =
                *reinterpret_cast<const uint4*>(Bhi + bsrc);
            *reinterpret_cast<uint4*>(sm + SB_LO + dst) =
                *reinterpret_cast<const uint4*>(Blo + bsrc);
        }
        __syncthreads();

        #pragma unroll
        for (int ks = 0; ks < 2; ks++) {
            const uint32_t koff = (uint32_t)ks * 32;
            uint32_t ah[4][4], al[4][4], bh[2][4], bl[2][4];
            #pragma unroll
            for (int mm = 0; mm < 4; mm++) {
                uint32_t ab = (uint32_t)(warp_m * 64 + mm * 16) * ROWB + koff + a_lane_off;
                ldsm_x4(ah[mm], smA_hi + ab);
                ldsm_x4(al[mm], smA_lo + ab);
            }
            #pragma unroll
            for (int pr = 0; pr < 2; pr++) {
                uint32_t bb = (uint32_t)(warp_n * 32 + pr * 16) * ROWB + koff + b_lane_off;
                ldsm_x4(bh[pr], smB_hi + bb);
                ldsm_x4(bl[pr], smB_lo + bb);
            }
            #pragma unroll
            for (int mm = 0; mm < 4; mm++) {
                #pragma unroll
                for (int nn = 0; nn < 4; nn++) {
                    const int pr = nn >> 1, sb2 = (nn & 1) * 2;
                    mma16816(acc[mm][nn], ah[mm], bh[pr][sb2], bh[pr][sb2 + 1]);
                    mma16816(acc[mm][nn], ah[mm], bl[pr][sb2], bl[pr][sb2 + 1]);
                    mma16816(acc[mm][nn], al[mm], bh[pr][sb2], bh[pr][sb2 + 1]);
                }
            }
        }
        __syncthreads();
    }

    const int g = lane >> 2, tq = lane & 3;
    #pragma unroll
    for (int mm = 0; mm < 4; mm++) {
        #pragma unroll
        for (int nn = 0; nn < 4; nn++) {
            int row = row0 + warp_m * 64 + mm * 16 + g;
            int col = col0 + warp_n * 32 + nn * 8 + tq * 2;
            if (Chi) {
                #pragma unroll
                for (int half = 0; half < 2; half++) {
                    float v0 = acc[mm][nn][half * 2 + 0];
                    float v1 = acc[mm][nn][half * 2 + 1];
                    float h0 = bf16_round(v0), h1 = bf16_round(v1);
                    size_t idx = (size_t)(row + half * 8) * Ntot + col;
                    *reinterpret_cast<uint32_t*>(Chi + idx) = pack_bf16x2(h0, h1);
                    *reinterpret_cast<uint32_t*>(Clo + idx) = pack_bf16x2(v0 - h0, v1 - h1);
                }
            } else {
                *reinterpret_cast<float2*>(&Cf[(size_t)row * Ntot + col]) =
                    make_float2(acc[mm][nn][0], acc[mm][nn][1]);
                *reinterpret_cast<float2*>(&Cf[(size_t)(row + 8) * Ntot + col]) =
                    make_float2(acc[mm][nn][2], acc[mm][nn][3]);
            }
        }
    }
}

// ---------------------------------------------------------------------------
// Flash attention via mma.sync, bf16 hi/lo split throughout.
// CTA = 128 q-rows x one (b,h). 8 warps x 16 q-rows. j-blocks of 64.
// Rows padded to 144B (9x16B units, gcd(9,8)=1 -> conflict-free ldmatrix).
// Writes y directly as bf16 hi/lo for the proj GEMM.
// ---------------------------------------------------------------------------
#define AROWB 144
#define SQ_HI 0
#define SQ_LO 18432
#define SK_HI 36864
#define SK_LO 46080
#define SV_HI 55296
#define SV_LO 64512
#define ATTN_SMEM 73728

__global__ __launch_bounds__(256) void mma_attn_kernel(
    const __nv_bfloat16* __restrict__ qkvh, const __nv_bfloat16* __restrict__ qkvl,
    __nv_bfloat16* __restrict__ yh, __nv_bfloat16* __restrict__ yl)
{
    extern __shared__ __align__(16) char sm[];
    const uint32_t smb = smem_u32(sm);
    const int tid = threadIdx.x;
    const int w = tid >> 5;
    const int lane = tid & 31;
    const int g = lane >> 2, tq = lane & 3;
    const int qb = blockIdx.x;
    const int bh = blockIdx.y;
    const int b = bh >> 4, h = bh & 15;

    // Stage Q tiles (128 x 64 bf16, hi+lo)
    #pragma unroll
    for (int i = 0; i < 4; i++) {
        int u = tid + i * 256;          // 0..1023
        int r = u >> 3, c = u & 7;
        uint32_t dst = (uint32_t)r * AROWB + (uint32_t)c * 16;
        size_t src = ((size_t)(b * SS + qb * 128 + r)) * (3 * DD) + h * HD + c * 8;
        *reinterpret_cast<uint4*>(sm + SQ_HI + dst) =
            *reinterpret_cast<const uint4*>(qkvh + src);
        *reinterpret_cast<uint4*>(sm + SQ_LO + dst) =
            *reinterpret_cast<const uint4*>(qkvl + src);
    }
    __syncthreads();

    // Q fragments (4 k16-steps, hi/lo)
    const uint32_t a_off = (uint32_t)(lane & 15) * AROWB + ((lane >> 4) & 1) * 16;
    uint32_t qfh[4][4], qfl[4][4];
    #pragma unroll
    for (int t = 0; t < 4; t++) {
        uint32_t base = (uint32_t)(w * 16) * AROWB + (uint32_t)t * 32 + a_off;
        ldsm_x4(qfh[t], smb + SQ_HI + base);
        ldsm_x4(qfl[t], smb + SQ_LO + base);
    }

    float yacc[8][4] = {};
    float m0 = -1e30f, m1 = -1e30f, l0 = 0.0f, l1 = 0.0f;

    const uint32_t b_off = ((uint32_t)((lane & 7) + ((lane >> 4) & 1) * 8)) * AROWB
                         + ((lane >> 3) & 1) * 16;
    const uint32_t v_off = (uint32_t)(lane & 15) * AROWB + ((lane >> 4) & 1) * 16;
    const int rowbase = qb * 128 + w * 16;

    const int njb = 2 * qb + 2;
    for (int jb = 0; jb < njb; jb++) {
        const int j0 = jb * 64;
        // Load K/V hi/lo tiles (64 x 64 each)
        #pragma unroll
        for (int i = 0; i < 2; i++) {
            int u = tid + i * 256;      // 0..511
            int r = u >> 3, c = u & 7;
            uint32_t dst = (uint32_t)r * AROWB + (uint32_t)c * 16;
            size_t krow = ((size_t)(b * SS + j0 + r)) * (3 * DD) + DD + h * HD + c * 8;
            size_t vrow = krow + DD;
            *reinterpret_cast<uint4*>(sm + SK_HI + dst) =
                *reinterpret_cast<const uint4*>(qkvh + krow);
            *reinterpret_cast<uint4*>(sm + SK_LO + dst) =
                *reinterpret_cast<const uint4*>(qkvl + krow);
            *reinterpret_cast<uint4*>(sm + SV_HI + dst) =
                *reinterpret_cast<const uint4*>(qkvh + vrow);
            *reinterpret_cast<uint4*>(sm + SV_LO + dst) =
                *reinterpret_cast<const uint4*>(qkvl + vrow);
        }
        __syncthreads();

        // S = Q K^T (split: hi*hi + hi*lo + lo*hi)
        float sacc[8][4] = {};
        #pragma unroll
        for (int t = 0; t < 4; t++) {
            uint32_t kh[4][4], kl[4][4];
            #pragma unroll
            for (int pr = 0; pr < 4; pr++) {
                uint32_t ad = (uint32_t)(pr * 16) * AROWB + (uint32_t)t * 32 + b_off;
                ldsm_x4(kh[pr], smb + SK_HI + ad);
                ldsm_x4(kl[pr], smb + SK_LO + ad);
            }
            #pragma unroll
            for (int nn = 0; nn < 8; nn++) {
                const int pr = nn >> 1, s2 = (nn & 1) * 2;
                mma16816(sacc[nn], qfh[t], kh[pr][s2], kh[pr][s2 + 1]);
                mma16816(sacc[nn], qfh[t], kl[pr][s2], kl[pr][s2 + 1]);
                mma16816(sacc[nn], qfl[t], kh[pr][s2], kh[pr][s2 + 1]);
            }
        }

        // Scale + causal mask
        #pragma unroll
        for (int nn = 0; nn < 8; nn++)
            #pragma unroll
            for (int e = 0; e < 4; e++) sacc[nn][e] *= 0.125f;

        if (j0 + 63 > rowbase) {
            const int r0 = rowbase + g, r1 = r0 + 8;
            #pragma unroll
            for (int nn = 0; nn < 8; nn++) {
                int col = j0 + nn * 8 + 2 * tq;
                if (col > r0)     sacc[nn][0] = -1e30f;
                if (col + 1 > r0) sacc[nn][1] = -1e30f;
                if (col > r1)     sacc[nn][2] = -1e30f;
                if (col + 1 > r1) sacc[nn][3] = -1e30f;
            }
        }

        // Online softmax (rows g and g+8)
        float mx0 = -1e30f, mx1 = -1e30f;
        #pragma unroll
        for (int nn = 0; nn < 8; nn++) {
            mx0 = fmaxf(mx0, fmaxf(sacc[nn][0], sacc[nn][1]));
            mx1 = fmaxf(mx1, fmaxf(sacc[nn][2], sacc[nn][3]));
        }
        mx0 = fmaxf(mx0, __shfl_xor_sync(0xffffffffu, mx0, 1));
        mx0 = fmaxf(mx0, __shfl_xor_sync(0xffffffffu, mx0, 2));
        mx1 = fmaxf(mx1, __shfl_xor_sync(0xffffffffu, mx1, 1));
        mx1 = fmaxf(mx1, __shfl_xor_sync(0xffffffffu, mx1, 2));

        float mn0 = fmaxf(m0, mx0), mn1 = fmaxf(m1, mx1);
        float f0 = __expf(m0 - mn0), f1 = __expf(m1 - mn1);
        m0 = mn0; m1 = mn1;

        float p[8][4];
        float ps0 = 0.0f, ps1 = 0.0f;
        #pragma unroll
        for (int nn = 0; nn < 8; nn++) {
            p[nn][0] = __expf(sacc[nn][0] - m0);
            p[nn][1] = __expf(sacc[nn][1] - m0);
            p[nn][2] = __expf(sacc[nn][2] - m1);
            p[nn][3] = __expf(sacc[nn][3] - m1);
            ps0 += p[nn][0] + p[nn][1];
            ps1 += p[nn][2] + p[nn][3];
        }
        ps0 += __shfl_xor_sync(0xffffffffu, ps0, 1);
        ps0 += __shfl_xor_sync(0xffffffffu, ps0, 2);
        ps1 += __shfl_xor_sync(0xffffffffu, ps1, 1);
        ps1 += __shfl_xor_sync(0xffffffffu, ps1, 2);
        l0 = l0 * f0 + ps0;
        l1 = l1 * f1 + ps1;

        #pragma unroll
        for (int nn = 0; nn < 8; nn++) {
            yacc[nn][0] *= f0; yacc[nn][1] *= f0;
            yacc[nn][2] *= f1; yacc[nn][3] *= f1;
        }

        // Pack P into A-fragments (hi/lo): k16-step t <- S tiles 2t, 2t+1
        uint32_t ph[4][4], pl[4][4];
        #pragma unroll
        for (int t = 0; t < 4; t++) {
            #pragma unroll
            for (int q2 = 0; q2 < 2; q2++) {       // tile 2t+q2 -> frag regs 2q2, 2q2+1
                const float* pp = p[2 * t + q2];
                float h0 = bf16_round(pp[0]), h1 = bf16_round(pp[1]);
                float h2 = bf16_round(pp[2]), h3 = bf16_round(pp[3]);
                ph[t][2 * q2 + 0] = pack_bf16x2(h0, h1);
                ph[t][2 * q2 + 1] = pack_bf16x2(h2, h3);
                pl[t][2 * q2 + 0] = pack_bf16x2(pp[0] - h0, pp[1] - h1);
                pl[t][2 * q2 + 1] = pack_bf16x2(pp[2] - h2, pp[3] - h3);
            }
        }

        // y += P V  (V B-fragments via ldmatrix.trans on [j][d] tiles)
        #pragma unroll
        for (int t = 0; t < 4; t++) {
            #pragma unroll
            for (int d16 = 0; d16 < 4; d16++) {
                uint32_t vh[4], vl[4];
                uint32_t ad = (uint32_t)(16 * t) * AROWB + (uint32_t)d16 * 32 + v_off;
                ldsm_x4_trans(vh, smb + SV_HI + ad);
                ldsm_x4_trans(vl, smb + SV_LO + ad);
                mma16816(yacc[2 * d16 + 0], ph[t], vh[0], vh[1]);
                mma16816(yacc[2 * d16 + 0], ph[t], vl[0], vl[1]);
                mma16816(yacc[2 * d16 + 0], pl[t], vh[0], vh[1]);
                mma16816(yacc[2 * d16 + 1], ph[t], vh[2], vh[3]);
                mma16816(yacc[2 * d16 + 1], ph[t], vl[2], vl[3]);
                mma16816(yacc[2 * d16 + 1], pl[t], vh[2], vh[3]);
            }
        }
        __syncthreads();
    }

    // Epilogue: y /= l, write bf16 hi/lo
    const float i0 = 1.0f / l0, i1 = 1.0f / l1;
    const int grow0 = b * SS + qb * 128 + w * 16 + g;
    #pragma unroll
    for (int nn = 0; nn < 8; nn++) {
        int col = h * HD + nn * 8 + 2 * tq;
        float v0 = yacc[nn][0] * i0, v1 = yacc[nn][1] * i0;
        float v2 = yacc[nn][2] * i1, v3 = yacc[nn][3] * i1;
        float h0 = bf16_round(v0), h1 = bf16_round(v1);
        float h2 = bf16_round(v2), h3 = bf16_round(v3);
        size_t idx0 = (size_t)grow0 * DD + col;
        size_t idx1 = (size_t)(grow0 + 8) * DD + col;
        *reinterpret_cast<uint32_t*>(yh + idx0) = pack_bf16x2(h0, h1);
        *reinterpret_cast<uint32_t*>(yl + idx0) = pack_bf16x2(v0 - h0, v1 - h1);
        *reinterpret_cast<uint32_t*>(yh + idx1) = pack_bf16x2(h2, h3);
        *reinterpret_cast<uint32_t*>(yl + idx1) = pack_bf16x2(v2 - h2, v3 - h3);
    }
}

// ---------------------------------------------------------------------------
// Launch
// ---------------------------------------------------------------------------
extern "C" void kernel_launch(void* const* d_in, const int* in_sizes, int n_in,
                              void* d_out, int out_size)
{
    const float* x      = (const float*)d_in[0];   // [2,2048,1024]
    const float* w_qkv  = (const float*)d_in[1];   // [1024,3072]
    const float* w_proj = (const float*)d_in[2];   // [1024,1024]
    float* out = (float*)d_out;                    // [2,2048,1024]

    __nv_bfloat16 *xhi, *xlo, *qkvh, *qkvl, *yh, *yl;
    __nv_bfloat16 *wqT_hi, *wqT_lo, *wpT_hi, *wpT_lo;
    cudaGetSymbolAddress((void**)&xhi, g_xhi);
    cudaGetSymbolAddress((void**)&xlo, g_xlo);
    cudaGetSymbolAddress((void**)&qkvh, g_qkvh);
    cudaGetSymbolAddress((void**)&qkvl, g_qkvl);
    cudaGetSymbolAddress((void**)&yh, g_yh);
    cudaGetSymbolAddress((void**)&yl, g_yl);
    cudaGetSymbolAddress((void**)&wqT_hi, g_wqkvT_hi);
    cudaGetSymbolAddress((void**)&wqT_lo, g_wqkvT_lo);
    cudaGetSymbolAddress((void**)&wpT_hi, g_wprojT_hi);
    cudaGetSymbolAddress((void**)&wpT_lo, g_wprojT_lo);

    cudaFuncSetAttribute(mma_attn_kernel,
                         cudaFuncAttributeMaxDynamicSharedMemorySize, ATTN_SMEM);

    const int M = BB * SS;       // 4096
    const int nElemX = M * DD;

    split_kernel<<<nElemX / 256, 256>>>(x, xhi, xlo, nElemX);
    transpose_split_kernel<<<dim3(3 * DD / 32, DD / 32), 256>>>(w_qkv, wqT_hi, wqT_lo, DD, 3 * DD);
    transpose_split_kernel<<<dim3(DD / 32, DD / 32), 256>>>(w_proj, wpT_hi, wpT_lo, DD, DD);

    // qkv = x @ w_qkv -> bf16 hi/lo directly
    mma_gemm_kernel<<<dim3(3 * DD / 128, M / 128), 256>>>(
        xhi, xlo, wqT_hi, wqT_lo, nullptr, qkvh, qkvl, 3 * DD, DD);

    // attention -> y bf16 hi/lo directly
    mma_attn_kernel<<<dim3(SS / 128, BB * NH), 256, ATTN_SMEM>>>(qkvh, qkvl, yh, yl);

    // out = y @ w_proj -> fp32
    mma_gemm_kernel<<<dim3(DD / 128, M / 128), 256>>>(
        yh, yl, wpT_hi, wpT_lo, out, nullptr, nullptr, DD, DD);
}

// round 5
// speedup vs baseline: 3.5404x; 1.6864x over previous
#include <cuda_runtime.h>
#include <cuda_bf16.h>
#include <cstdint>

// Problem constants: B=2, S=2048, D=1024, H=16, HD=64
#define BB 2
#define SS 2048
#define DD 1024
#define NH 16
#define HD 64

// ---------------------------------------------------------------------------
// mma.sync / ldmatrix / cp.async helpers (plain PTX, no sm_103a-gated features)
// ---------------------------------------------------------------------------
__device__ __forceinline__ uint32_t smem_u32(const void* p) {
    uint32_t a;
    asm("{ .reg .u64 t; cvta.to.shared.u64 t, %1; cvt.u32.u64 %0, t; }"
        : "=r"(a) : "l"(p));
    return a;
}
__device__ __forceinline__ void ldsm_x4(uint32_t* r, uint32_t addr) {
    asm volatile("ldmatrix.sync.aligned.m8n8.x4.shared.b16 {%0,%1,%2,%3}, [%4];"
        : "=r"(r[0]), "=r"(r[1]), "=r"(r[2]), "=r"(r[3]) : "r"(addr));
}
__device__ __forceinline__ void ldsm_x4_trans(uint32_t* r, uint32_t addr) {
    asm volatile("ldmatrix.sync.aligned.m8n8.x4.trans.shared.b16 {%0,%1,%2,%3}, [%4];"
        : "=r"(r[0]), "=r"(r[1]), "=r"(r[2]), "=r"(r[3]) : "r"(addr));
}
__device__ __forceinline__ void mma16816(float* c, const uint32_t* a,
                                         uint32_t b0, uint32_t b1) {
    asm volatile(
        "mma.sync.aligned.m16n8k16.row.col.f32.bf16.bf16.f32 "
        "{%0,%1,%2,%3}, {%4,%5,%6,%7}, {%8,%9}, {%0,%1,%2,%3};"
        : "+f"(c[0]), "+f"(c[1]), "+f"(c[2]), "+f"(c[3])
        : "r"(a[0]), "r"(a[1]), "r"(a[2]), "r"(a[3]), "r"(b0), "r"(b1));
}
__device__ __forceinline__ void cp_async16(uint32_t dst, const void* src) {
    asm volatile("cp.async.cg.shared.global [%0], [%1], 16;"
        :: "r"(dst), "l"(src));
}
#define CP_COMMIT() asm volatile("cp.async.commit_group;" ::: "memory")
#define CP_WAIT(n)  asm volatile("cp.async.wait_group %0;" :: "n"(n) : "memory")

// pack: low half = first arg, high half = second arg
__device__ __forceinline__ uint32_t pack_bf16x2(float lo_elem, float hi_elem) {
    uint32_t r;
    asm("cvt.rn.bf16x2.f32 %0, %1, %2;" : "=r"(r) : "f"(hi_elem), "f"(lo_elem));
    return r;
}
__device__ __forceinline__ float bf16_round(float v) {
    return __bfloat162float(__float2bfloat16(v));
}

// ---------------------------------------------------------------------------
// Scratch (__device__ globals; allocation-free rule)
// ---------------------------------------------------------------------------
__device__ __nv_bfloat16 g_xhi[(size_t)BB * SS * DD];
__device__ __nv_bfloat16 g_xlo[(size_t)BB * SS * DD];
__device__ __nv_bfloat16 g_qkvh[(size_t)BB * SS * 3 * DD];
__device__ __nv_bfloat16 g_qkvl[(size_t)BB * SS * 3 * DD];
__device__ __nv_bfloat16 g_yh[(size_t)BB * SS * DD];
__device__ __nv_bfloat16 g_yl[(size_t)BB * SS * DD];
__device__ __nv_bfloat16 g_wqkvT_hi[(size_t)3 * DD * DD];
__device__ __nv_bfloat16 g_wqkvT_lo[(size_t)3 * DD * DD];
__device__ __nv_bfloat16 g_wprojT_hi[(size_t)DD * DD];
__device__ __nv_bfloat16 g_wprojT_lo[(size_t)DD * DD];

// ---------------------------------------------------------------------------
// Elementwise fp32 -> bf16 hi/lo split (input x only)
// ---------------------------------------------------------------------------
__global__ __launch_bounds__(256) void split_kernel(
    const float* __restrict__ in, __nv_bfloat16* __restrict__ hi,
    __nv_bfloat16* __restrict__ lo, int n)
{
    int i = blockIdx.x * 256 + threadIdx.x;
    if (i < n) {
        float v = in[i];
        __nv_bfloat16 h = __float2bfloat16(v);
        hi[i] = h;
        lo[i] = __float2bfloat16(v - __bfloat162float(h));
    }
}

// ---------------------------------------------------------------------------
// Transpose + split: in [K,N] fp32 -> hiT/loT [N,K] bf16 (K-major)
// ---------------------------------------------------------------------------
__global__ __launch_bounds__(256) void transpose_split_kernel(
    const float* __restrict__ in, __nv_bfloat16* __restrict__ hiT,
    __nv_bfloat16* __restrict__ loT, int K, int N)
{
    __shared__ float t[32][33];
    const int tx = threadIdx.x & 31;
    const int ty = threadIdx.x >> 5;
    const int n0 = blockIdx.x * 32;
    const int k0 = blockIdx.y * 32;
    #pragma unroll
    for (int i = 0; i < 4; i++) {
        int k = k0 + ty + i * 8;
        t[ty + i * 8][tx] = in[(size_t)k * N + n0 + tx];
    }
    __syncthreads();
    #pragma unroll
    for (int i = 0; i < 4; i++) {
        int n = n0 + ty + i * 8;
        int k = k0 + tx;
        float v = t[tx][ty + i * 8];
        __nv_bfloat16 h = __float2bfloat16(v);
        hiT[(size_t)n * K + k] = h;
        loT[(size_t)n * K + k] = __float2bfloat16(v - __bfloat162float(h));
    }
}

// ---------------------------------------------------------------------------
// bf16-split GEMM via mma.sync, cp.async 2-stage pipelined.
// C = (Ahi+Alo)[M,K] @ (Bhi+Blo)[N,K]^T ; D = hh + hl + lh, fp32 accumulate.
// CTA 128x128, BK=32, 256 threads (8 warps 2x4), warp tile 64x32.
// ---------------------------------------------------------------------------
#define ROWB 80
#define GSTAGE 40960
#define SA_HI 0
#define SA_LO 10240
#define SB_HI 20480
#define SB_LO 30720
#define GEMM_SMEM (2 * GSTAGE)

__global__ __launch_bounds__(256, 2) void mma_gemm_kernel(
    const __nv_bfloat16* __restrict__ Ahi, const __nv_bfloat16* __restrict__ Alo,
    const __nv_bfloat16* __restrict__ Bhi, const __nv_bfloat16* __restrict__ Blo,
    float* __restrict__ Cf, __nv_bfloat16* __restrict__ Chi,
    __nv_bfloat16* __restrict__ Clo, int Ntot, int K)
{
    extern __shared__ __align__(16) char sm[];
    const uint32_t smb = smem_u32(sm);

    const int tid = threadIdx.x;
    const int wid = tid >> 5;
    const int lane = tid & 31;
    const int warp_m = wid >> 2;
    const int warp_n = wid & 3;
    const int row0 = blockIdx.y * 128;
    const int col0 = blockIdx.x * 128;

    const uint32_t a_lane_off = (uint32_t)(lane & 15) * ROWB + ((lane >> 4) & 1) * 16;
    const uint32_t b_lane_off = ((uint32_t)((lane & 7) + ((lane >> 4) & 1) * 8)) * ROWB
                              + ((lane >> 3) & 1) * 16;

    // per-thread load coords (2 uint4 per tile)
    const int l_r0 = tid >> 2, l_c = (tid & 3);
    const uint32_t l_dst0 = (uint32_t)l_r0 * ROWB + (uint32_t)l_c * 16;
    const uint32_t l_dst1 = (uint32_t)(l_r0 + 64) * ROWB + (uint32_t)l_c * 16;

    auto load_stage = [&](int kc, int st) {
        const int k0 = kc << 5;
        const uint32_t base = smb + (uint32_t)st * GSTAGE;
        size_t a0 = (size_t)(row0 + l_r0) * K + k0 + l_c * 8;
        size_t b0 = (size_t)(col0 + l_r0) * K + k0 + l_c * 8;
        size_t a1 = a0 + (size_t)64 * K;
        size_t b1 = b0 + (size_t)64 * K;
        cp_async16(base + SA_HI + l_dst0, Ahi + a0);
        cp_async16(base + SA_HI + l_dst1, Ahi + a1);
        cp_async16(base + SA_LO + l_dst0, Alo + a0);
        cp_async16(base + SA_LO + l_dst1, Alo + a1);
        cp_async16(base + SB_HI + l_dst0, Bhi + b0);
        cp_async16(base + SB_HI + l_dst1, Bhi + b1);
        cp_async16(base + SB_LO + l_dst0, Blo + b0);
        cp_async16(base + SB_LO + l_dst1, Blo + b1);
    };

    float acc[4][4][4] = {};

    const int nchunks = K >> 5;
    load_stage(0, 0);
    CP_COMMIT();

    for (int kc = 0; kc < nchunks; kc++) {
        if (kc + 1 < nchunks) {
            load_stage(kc + 1, (kc + 1) & 1);
            CP_COMMIT();
            CP_WAIT(1);
        } else {
            CP_WAIT(0);
        }
        __syncthreads();

        const uint32_t stb = smb + (uint32_t)(kc & 1) * GSTAGE;
        #pragma unroll
        for (int ks = 0; ks < 2; ks++) {
            const uint32_t koff = (uint32_t)ks * 32;
            uint32_t ah[4][4], al[4][4], bh[2][4], bl[2][4];
            #pragma unroll
            for (int mm = 0; mm < 4; mm++) {
                uint32_t ab = (uint32_t)(warp_m * 64 + mm * 16) * ROWB + koff + a_lane_off;
                ldsm_x4(ah[mm], stb + SA_HI + ab);
                ldsm_x4(al[mm], stb + SA_LO + ab);
            }
            #pragma unroll
            for (int pr = 0; pr < 2; pr++) {
                uint32_t bb = (uint32_t)(warp_n * 32 + pr * 16) * ROWB + koff + b_lane_off;
                ldsm_x4(bh[pr], stb + SB_HI + bb);
                ldsm_x4(bl[pr], stb + SB_LO + bb);
            }
            #pragma unroll
            for (int mm = 0; mm < 4; mm++) {
                #pragma unroll
                for (int nn = 0; nn < 4; nn++) {
                    const int pr = nn >> 1, sb2 = (nn & 1) * 2;
                    mma16816(acc[mm][nn], ah[mm], bh[pr][sb2], bh[pr][sb2 + 1]);
                    mma16816(acc[mm][nn], ah[mm], bl[pr][sb2], bl[pr][sb2 + 1]);
                    mma16816(acc[mm][nn], al[mm], bh[pr][sb2], bh[pr][sb2 + 1]);
                }
            }
        }
        __syncthreads();
    }

    const int g = lane >> 2, tq = lane & 3;
    #pragma unroll
    for (int mm = 0; mm < 4; mm++) {
        #pragma unroll
        for (int nn = 0; nn < 4; nn++) {
            int row = row0 + warp_m * 64 + mm * 16 + g;
            int col = col0 + warp_n * 32 + nn * 8 + tq * 2;
            if (Chi) {
                #pragma unroll
                for (int half = 0; half < 2; half++) {
                    float v0 = acc[mm][nn][half * 2 + 0];
                    float v1 = acc[mm][nn][half * 2 + 1];
                    float h0 = bf16_round(v0), h1 = bf16_round(v1);
                    size_t idx = (size_t)(row + half * 8) * Ntot + col;
                    *reinterpret_cast<uint32_t*>(Chi + idx) = pack_bf16x2(h0, h1);
                    *reinterpret_cast<uint32_t*>(Clo + idx) = pack_bf16x2(v0 - h0, v1 - h1);
                }
            } else {
                *reinterpret_cast<float2*>(&Cf[(size_t)row * Ntot + col]) =
                    make_float2(acc[mm][nn][0], acc[mm][nn][1]);
                *reinterpret_cast<float2*>(&Cf[(size_t)(row + 8) * Ntot + col]) =
                    make_float2(acc[mm][nn][2], acc[mm][nn][3]);
            }
        }
    }
}

// ---------------------------------------------------------------------------
// Flash attention via mma.sync, bf16 hi/lo split, cp.async 2-stage KV pipeline.
// CTA = 128 q-rows x one (b,h). 8 warps x 16 q-rows. j-blocks of 64.
// Rows padded to 144B (9x16B, gcd(9,8)=1 -> conflict-free ldmatrix).
// Warps whose strip is fully above the diagonal skip the block's compute.
// ---------------------------------------------------------------------------
#define AROWB 144
#define SQ_HI 0
#define SQ_LO 18432
#define AKV0 36864
#define ASTAGE 36864
#define AK_HI 0
#define AK_LO 9216
#define AV_HI 18432
#define AV_LO 27648
#define ATTN_SMEM (AKV0 + 2 * ASTAGE)

__global__ __launch_bounds__(256) void mma_attn_kernel(
    const __nv_bfloat16* __restrict__ qkvh, const __nv_bfloat16* __restrict__ qkvl,
    __nv_bfloat16* __restrict__ yh, __nv_bfloat16* __restrict__ yl)
{
    extern __shared__ __align__(16) char sm[];
    const uint32_t smb = smem_u32(sm);
    const int tid = threadIdx.x;
    const int w = tid >> 5;
    const int lane = tid & 31;
    const int g = lane >> 2, tq = lane & 3;
    const int qb = blockIdx.x;
    const int bh = blockIdx.y;
    const int b = bh >> 4, h = bh & 15;

    // per-thread KV load coords (2 uint4 per tile)
    const int kv_r0 = tid >> 3, kv_c = tid & 7;
    const uint32_t kv_dst0 = (uint32_t)kv_r0 * AROWB + (uint32_t)kv_c * 16;
    const uint32_t kv_dst1 = (uint32_t)(kv_r0 + 32) * AROWB + (uint32_t)kv_c * 16;

    auto load_kv = [&](int jb, int st) {
        const int j0 = jb * 64;
        const uint32_t base = smb + AKV0 + (uint32_t)st * ASTAGE;
        size_t k0s = ((size_t)(b * SS + j0 + kv_r0)) * (3 * DD) + DD + h * HD + kv_c * 8;
        size_t k1s = k0s + (size_t)32 * (3 * DD);
        cp_async16(base + AK_HI + kv_dst0, qkvh + k0s);
        cp_async16(base + AK_HI + kv_dst1, qkvh + k1s);
        cp_async16(base + AK_LO + kv_dst0, qkvl + k0s);
        cp_async16(base + AK_LO + kv_dst1, qkvl + k1s);
        cp_async16(base + AV_HI + kv_dst0, qkvh + k0s + DD);
        cp_async16(base + AV_HI + kv_dst1, qkvh + k1s + DD);
        cp_async16(base + AV_LO + kv_dst0, qkvl + k0s + DD);
        cp_async16(base + AV_LO + kv_dst1, qkvl + k1s + DD);
    };

    // Stage Q tiles (128 x 64 bf16, hi+lo)
    #pragma unroll
    for (int i = 0; i < 4; i++) {
        int u = tid + i * 256;
        int r = u >> 3, c = u & 7;
        uint32_t dst = (uint32_t)r * AROWB + (uint32_t)c * 16;
        size_t src = ((size_t)(b * SS + qb * 128 + r)) * (3 * DD) + h * HD + c * 8;
        cp_async16(smb + SQ_HI + dst, qkvh + src);
        cp_async16(smb + SQ_LO + dst, qkvl + src);
    }
    CP_COMMIT();

    // Prefetch first KV block
    load_kv(0, 0);
    CP_COMMIT();

    // Wait for Q (two groups in flight: wait until <=1 pending means Q done)
    CP_WAIT(1);
    __syncthreads();

    const uint32_t a_off = (uint32_t)(lane & 15) * AROWB + ((lane >> 4) & 1) * 16;
    uint32_t qfh[4][4], qfl[4][4];
    #pragma unroll
    for (int t = 0; t < 4; t++) {
        uint32_t base = (uint32_t)(w * 16) * AROWB + (uint32_t)t * 32 + a_off;
        ldsm_x4(qfh[t], smb + SQ_HI + base);
        ldsm_x4(qfl[t], smb + SQ_LO + base);
    }

    float yacc[8][4] = {};
    float m0 = -1e30f, m1 = -1e30f, l0 = 0.0f, l1 = 0.0f;

    const uint32_t b_off = ((uint32_t)((lane & 7) + ((lane >> 4) & 1) * 8)) * AROWB
                         + ((lane >> 3) & 1) * 16;
    const uint32_t v_off = (uint32_t)(lane & 15) * AROWB + ((lane >> 4) & 1) * 16;
    const int rowbase = qb * 128 + w * 16;

    const int njb = 2 * qb + 2;
    for (int jb = 0; jb < njb; jb++) {
        const int j0 = jb * 64;
        if (jb + 1 < njb) {
            load_kv(jb + 1, (jb + 1) & 1);
            CP_COMMIT();
            CP_WAIT(1);
        } else {
            CP_WAIT(0);
        }
        __syncthreads();

        if (j0 <= rowbase + 15) {   // strip not fully above diagonal
            const uint32_t kvb = smb + AKV0 + (uint32_t)(jb & 1) * ASTAGE;

            // S = Q K^T (hi*hi + hi*lo + lo*hi)
            float sacc[8][4] = {};
            #pragma unroll
            for (int t = 0; t < 4; t++) {
                uint32_t kh[4][4], kl[4][4];
                #pragma unroll
                for (int pr = 0; pr < 4; pr++) {
                    uint32_t ad = (uint32_t)(pr * 16) * AROWB + (uint32_t)t * 32 + b_off;
                    ldsm_x4(kh[pr], kvb + AK_HI + ad);
                    ldsm_x4(kl[pr], kvb + AK_LO + ad);
                }
                #pragma unroll
                for (int nn = 0; nn < 8; nn++) {
                    const int pr = nn >> 1, s2 = (nn & 1) * 2;
                    mma16816(sacc[nn], qfh[t], kh[pr][s2], kh[pr][s2 + 1]);
                    mma16816(sacc[nn], qfh[t], kl[pr][s2], kl[pr][s2 + 1]);
                    mma16816(sacc[nn], qfl[t], kh[pr][s2], kh[pr][s2 + 1]);
                }
            }

            #pragma unroll
            for (int nn = 0; nn < 8; nn++)
                #pragma unroll
                for (int e = 0; e < 4; e++) sacc[nn][e] *= 0.125f;

            if (j0 + 63 > rowbase) {
                const int r0 = rowbase + g, r1 = r0 + 8;
                #pragma unroll
                for (int nn = 0; nn < 8; nn++) {
                    int col = j0 + nn * 8 + 2 * tq;
                    if (col > r0)     sacc[nn][0] = -1e30f;
                    if (col + 1 > r0) sacc[nn][1] = -1e30f;
                    if (col > r1)     sacc[nn][2] = -1e30f;
                    if (col + 1 > r1) sacc[nn][3] = -1e30f;
                }
            }

            // Online softmax (rows g, g+8)
            float mx0 = -1e30f, mx1 = -1e30f;
            #pragma unroll
            for (int nn = 0; nn < 8; nn++) {
                mx0 = fmaxf(mx0, fmaxf(sacc[nn][0], sacc[nn][1]));
                mx1 = fmaxf(mx1, fmaxf(sacc[nn][2], sacc[nn][3]));
            }
            mx0 = fmaxf(mx0, __shfl_xor_sync(0xffffffffu, mx0, 1));
            mx0 = fmaxf(mx0, __shfl_xor_sync(0xffffffffu, mx0, 2));
            mx1 = fmaxf(mx1, __shfl_xor_sync(0xffffffffu, mx1, 1));
            mx1 = fmaxf(mx1, __shfl_xor_sync(0xffffffffu, mx1, 2));

            float mn0 = fmaxf(m0, mx0), mn1 = fmaxf(m1, mx1);
            float f0 = __expf(m0 - mn0), f1 = __expf(m1 - mn1);
            m0 = mn0; m1 = mn1;

            float p[8][4];
            float ps0 = 0.0f, ps1 = 0.0f;
            #pragma unroll
            for (int nn = 0; nn < 8; nn++) {
                p[nn][0] = __expf(sacc[nn][0] - m0);
                p[nn][1] = __expf(sacc[nn][1] - m0);
                p[nn][2] = __expf(sacc[nn][2] - m1);
                p[nn][3] = __expf(sacc[nn][3] - m1);
                ps0 += p[nn][0] + p[nn][1];
                ps1 += p[nn][2] + p[nn][3];
            }
            ps0 += __shfl_xor_sync(0xffffffffu, ps0, 1);
            ps0 += __shfl_xor_sync(0xffffffffu, ps0, 2);
            ps1 += __shfl_xor_sync(0xffffffffu, ps1, 1);
            ps1 += __shfl_xor_sync(0xffffffffu, ps1, 2);
            l0 = l0 * f0 + ps0;
            l1 = l1 * f1 + ps1;

            #pragma unroll
            for (int nn = 0; nn < 8; nn++) {
                yacc[nn][0] *= f0; yacc[nn][1] *= f0;
                yacc[nn][2] *= f1; yacc[nn][3] *= f1;
            }

            // Pack P into A-fragments (hi/lo)
            uint32_t ph[4][4], pl[4][4];
            #pragma unroll
            for (int t = 0; t < 4; t++) {
                #pragma unroll
                for (int q2 = 0; q2 < 2; q2++) {
                    const float* pp = p[2 * t + q2];
                    float h0 = bf16_round(pp[0]), h1 = bf16_round(pp[1]);
                    float h2 = bf16_round(pp[2]), h3 = bf16_round(pp[3]);
                    ph[t][2 * q2 + 0] = pack_bf16x2(h0, h1);
                    ph[t][2 * q2 + 1] = pack_bf16x2(h2, h3);
                    pl[t][2 * q2 + 0] = pack_bf16x2(pp[0] - h0, pp[1] - h1);
                    pl[t][2 * q2 + 1] = pack_bf16x2(pp[2] - h2, pp[3] - h3);
                }
            }

            // y += P V (V via ldmatrix.trans)
            #pragma unroll
            for (int t = 0; t < 4; t++) {
                #pragma unroll
                for (int d16 = 0; d16 < 4; d16++) {
                    uint32_t vh[4], vl[4];
                    uint32_t ad = (uint32_t)(16 * t) * AROWB + (uint32_t)d16 * 32 + v_off;
                    ldsm_x4_trans(vh, kvb + AV_HI + ad);
                    ldsm_x4_trans(vl, kvb + AV_LO + ad);
                    mma16816(yacc[2 * d16 + 0], ph[t], vh[0], vh[1]);
                    mma16816(yacc[2 * d16 + 0], ph[t], vl[0], vl[1]);
                    mma16816(yacc[2 * d16 + 0], pl[t], vh[0], vh[1]);
                    mma16816(yacc[2 * d16 + 1], ph[t], vh[2], vh[3]);
                    mma16816(yacc[2 * d16 + 1], ph[t], vl[2], vl[3]);
                    mma16816(yacc[2 * d16 + 1], pl[t], vh[2], vh[3]);
                }
            }
        }
        __syncthreads();
    }

    // Epilogue: y /= l, write bf16 hi/lo
    const float i0 = 1.0f / l0, i1 = 1.0f / l1;
    const int grow0 = b * SS + qb * 128 + w * 16 + g;
    #pragma unroll
    for (int nn = 0; nn < 8; nn++) {
        int col = h * HD + nn * 8 + 2 * tq;
        float v0 = yacc[nn][0] * i0, v1 = yacc[nn][1] * i0;
        float v2 = yacc[nn][2] * i1, v3 = yacc[nn][3] * i1;
        float h0 = bf16_round(v0), h1 = bf16_round(v1);
        float h2 = bf16_round(v2), h3 = bf16_round(v3);
        size_t idx0 = (size_t)grow0 * DD + col;
        size_t idx1 = (size_t)(grow0 + 8) * DD + col;
        *reinterpret_cast<uint32_t*>(yh + idx0) = pack_bf16x2(h0, h1);
        *reinterpret_cast<uint32_t*>(yl + idx0) = pack_bf16x2(v0 - h0, v1 - h1);
        *reinterpret_cast<uint32_t*>(yh + idx1) = pack_bf16x2(h2, h3);
        *reinterpret_cast<uint32_t*>(yl + idx1) = pack_bf16x2(v2 - h2, v3 - h3);
    }
}

// ---------------------------------------------------------------------------
// Launch
// ---------------------------------------------------------------------------
extern "C" void kernel_launch(void* const* d_in, const int* in_sizes, int n_in,
                              void* d_out, int out_size)
{
    const float* x      = (const float*)d_in[0];
    const float* w_qkv  = (const float*)d_in[1];
    const float* w_proj = (const float*)d_in[2];
    float* out = (float*)d_out;

    __nv_bfloat16 *xhi, *xlo, *qkvh, *qkvl, *yh, *yl;
    __nv_bfloat16 *wqT_hi, *wqT_lo, *wpT_hi, *wpT_lo;
    cudaGetSymbolAddress((void**)&xhi, g_xhi);
    cudaGetSymbolAddress((void**)&xlo, g_xlo);
    cudaGetSymbolAddress((void**)&qkvh, g_qkvh);
    cudaGetSymbolAddress((void**)&qkvl, g_qkvl);
    cudaGetSymbolAddress((void**)&yh, g_yh);
    cudaGetSymbolAddress((void**)&yl, g_yl);
    cudaGetSymbolAddress((void**)&wqT_hi, g_wqkvT_hi);
    cudaGetSymbolAddress((void**)&wqT_lo, g_wqkvT_lo);
    cudaGetSymbolAddress((void**)&wpT_hi, g_wprojT_hi);
    cudaGetSymbolAddress((void**)&wpT_lo, g_wprojT_lo);

    cudaFuncSetAttribute(mma_gemm_kernel,
                         cudaFuncAttributeMaxDynamicSharedMemorySize, GEMM_SMEM);
    cudaFuncSetAttribute(mma_attn_kernel,
                         cudaFuncAttributeMaxDynamicSharedMemorySize, ATTN_SMEM);

    const int M = BB * SS;
    const int nElemX = M * DD;

    split_kernel<<<nElemX / 256, 256>>>(x, xhi, xlo, nElemX);
    transpose_split_kernel<<<dim3(3 * DD / 32, DD / 32), 256>>>(w_qkv, wqT_hi, wqT_lo, DD, 3 * DD);
    transpose_split_kernel<<<dim3(DD / 32, DD / 32), 256>>>(w_proj, wpT_hi, wpT_lo, DD, DD);

    mma_gemm_kernel<<<dim3(3 * DD / 128, M / 128), 256, GEMM_SMEM>>>(
        xhi, xlo, wqT_hi, wqT_lo, nullptr, qkvh, qkvl, 3 * DD, DD);

    mma_attn_kernel<<<dim3(SS / 128, BB * NH), 256, ATTN_SMEM>>>(qkvh, qkvl, yh, yl);

    mma_gemm_kernel<<<dim3(DD / 128, M / 128), 256, GEMM_SMEM>>>(
        yh, yl, wpT_hi, wpT_lo, out, nullptr, nullptr, DD, DD);
}